// round 13
// baseline (speedup 1.0000x reference)
#include <cuda_runtime.h>
#include <math.h>

#define DD 256
#define HH 512
#define BB 128
typedef unsigned long long ull;

__device__ __forceinline__ ull packf2(float lo, float hi) {
    return ((ull)__float_as_uint(hi) << 32) | (ull)__float_as_uint(lo);
}
__device__ __forceinline__ float lof(ull v) { return __uint_as_float((unsigned)v); }
__device__ __forceinline__ float hif(ull v) { return __uint_as_float((unsigned)(v >> 32)); }
__device__ __forceinline__ void ffma2(ull& d, ull a, ull b) {
    asm("fma.rn.f32x2 %0, %1, %2, %0;" : "+l"(d) : "l"(a), "l"(b));
}
#define BAR_SYNC(id)   asm volatile("bar.sync %0, 544;"   :: "r"(id) : "memory")
#define BAR_ARRIVE(id) asm volatile("bar.arrive %0, 544;" :: "r"(id) : "memory")
#define BPARP0 1   // +0/+1 : par pair-buffer ready
#define BPUBP0 3   // +0/+1 : pub pair-buffer ready

// Wide weights (layout identical to the 107us kernel)
__device__ ulonglong2 g_wA[260 * 512];
__device__ ull g_wA2[260 * 512];
__device__ ull g_wO[260 * 512];
__device__ ull g_w3p[2 * 512];
__device__ float g_w3o[2 * 512];
// Universal combiner records: per step, 136 floats
//  w0[d][s][n]           @ d*6+s*2+n        d=0..2 (ncol(i-3+d))
//  b0[s][n]              @ 18+s*2+n
//  b1[s][n]              @ 24+s*2+n
//  W1[l][sp][sc][n]      @ 32+l*18+sp*6+sc*2+n   l=0..3 (S(i-3+l))
//  Wo[l][sp][n]          @ 104+l*6+sp*2+n
//  bo[n]                 @ 128+n
__device__ float g_recU[256 * 136];

__device__ __forceinline__ int permf(int p) {
    if (p < 3) return (p == 0) ? 0 : ((p == 1) ? 255 : 510);
    if (p < 6) { int q = p - 3; return (q == 0) ? 1 : ((q == 1) ? 256 : 511); }
    int d = 3 + ((p - 6) >> 1);
    return (((p - 6) & 1) == 0) ? (d - 1) : (d + 254);
}
__device__ __forceinline__ int degf(int p) {
    if (p < 3) return 1;
    if (p < 6) return 2;
    return 3 + ((p - 6) >> 1);
}
__device__ __forceinline__ int Pof(int k) {
    if (k <= 0) return 0;
    if (k == 1) return 3;
    int v = 2 * k + 2;
    return v > HH ? HH : v;
}
__device__ __forceinline__ int ccf(int d) {
    if (d <= 0 || d > 255) return 0;
    return (d <= 2) ? 3 : 2;
}
__device__ __forceinline__ float elu1(float a) {
    float e = __expf(a) - 1.f;
    return a > 0.f ? a : e;
}

__global__ void setup_kernel(
    const float* __restrict__ W0m, const float* __restrict__ W1m, const float* __restrict__ Wom,
    const float* __restrict__ b0m, const float* __restrict__ b1m,
    const float* __restrict__ W0l, const float* __restrict__ W1l, const float* __restrict__ Wol,
    const float* __restrict__ b0l, const float* __restrict__ b1l,
    const float* __restrict__ bom, const float* __restrict__ bol)
{
    int tid = blockIdx.x * blockDim.x + threadIdx.x;
    int stride = gridDim.x * blockDim.x;

    // ---- wide arrays (unchanged semantics) ----
    for (int idx = tid; idx < 256 * 512; idx += stride) {
        int i = idx >> 9, u = idx & 511;
        int du = degf(u), ou = permf(u);
        int onet = u >> 8, ocol = u & 255;
        const float* Wo = onet ? Wol : Wom;

        int w0row = i - 1 < 0 ? 0 : i - 1;
        float m0 = (du >= w0row + 1) ? 1.f : 0.f;
        float w0mu = m0 * W0m[ou * DD + w0row];
        float w0lv = m0 * W0l[ou * DD + w0row];

        int pB = Pof(i - 2);
        float w1s[2][2], wos[2];
#pragma unroll
        for (int s = 0; s < 2; s++) {
            int p = pB + s; if (p > HH - 1) p = HH - 1;
            int op = permf(p), dp = degf(p);
            float m1 = (du >= dp) ? 1.f : 0.f;
            w1s[s][0] = m1 * W1m[ou * HH + op];
            w1s[s][1] = m1 * W1l[ou * HH + op];
            float mo = (ocol >= dp) ? 1.f : 0.f;
            wos[s] = mo * Wo[ocol * HH + op];
        }
        g_wA[i * 512 + u] = make_ulonglong2(packf2(w0mu, w0lv), packf2(w1s[0][0], w1s[0][1]));
        g_wA2[i * 512 + u] = packf2(w1s[1][0], w1s[1][1]);
        g_wO[i * 512 + u] = packf2(wos[0], wos[1]);
    }
    for (int idx = tid; idx < 1024; idx += stride) {
        int j = idx >> 9, u = idx & 511;
        int du = degf(u), ou = permf(u);
        int onet = u >> 8, ocol = u & 255;
        const float* Wo = onet ? Wol : Wom;
        int p = (j == 0) ? 2 : 5;
        int op = permf(p), dp = degf(p);
        float m1 = (du >= dp) ? 1.f : 0.f;
        float mo = (ocol >= dp) ? 1.f : 0.f;
        g_w3p[idx] = packf2(m1 * W1m[ou * HH + op], m1 * W1l[ou * HH + op]);
        g_w3o[idx] = mo * Wo[ocol * HH + op];
    }

    // ---- universal combiner records ----
    for (int i = tid; i < 256; i += stride) {
        float* r = g_recU + i * 136;
        for (int k = 0; k < 136; k++) r[k] = 0.f;
        const int cc = ccf(i);
        const int cB = Pof(i - 1);
        const bool oddi = (i & 1) != 0;
        for (int s = 0; s < cc; s++) {
            int u = permf(cB + s);
            for (int d = 0; d < 3; d++) {
                int j = i - 3 + d;
                if (j >= 0 && (oddi || d > 0)) {
                    r[d * 6 + s * 2 + 0] = W0m[u * DD + j];
                    r[d * 6 + s * 2 + 1] = W0l[u * DD + j];
                }
            }
            r[18 + s * 2 + 0] = b0m[u]; r[18 + s * 2 + 1] = b0l[u];
            r[24 + s * 2 + 0] = b1m[u]; r[24 + s * 2 + 1] = b1l[u];
        }
        for (int l = 0; l < 4; l++) {
            int dlev = i - 3 + l;
            if (dlev < 1) continue;
            if (!oddi && l == 0) continue;   // even step: deepest level lives in par
            int cl = ccf(dlev);
            int lB = Pof(dlev - 1);
            for (int sp = 0; sp < cl; sp++) {
                int p = permf(lB + sp);
                r[104 + l * 6 + sp * 2 + 0] = Wom[i * HH + p];
                r[104 + l * 6 + sp * 2 + 1] = Wol[i * HH + p];
                for (int sc = 0; sc < cc; sc++) {
                    int g = permf(cB + sc);
                    r[32 + l * 18 + sp * 6 + sc * 2 + 0] = W1m[g * HH + p];
                    r[32 + l * 18 + sp * 6 + sc * 2 + 1] = W1l[g * HH + p];
                }
            }
        }
        r[128] = bom[i]; r[129] = bol[i];
    }
}

struct CU {
    float nc1, nc2, nc3, lvsum;
    float h0[3][3][2];   // [lvl 0=oldest][slot][net]
    float h1[3][3][2];
};

// one combiner step from a universal record
__device__ __forceinline__ void comb_u(
    const float* __restrict__ par, float* __restrict__ pub,
    const float* __restrict__ rr, float xi,
    CU& st, float* __restrict__ outp, bool lead)
{
    float pp[16];
#pragma unroll
    for (int k = 0; k < 4; k++) *(float4*)(pp + 4 * k) = *(const float4*)(par + 4 * k);

    float h0c[3][2];
#pragma unroll
    for (int s = 0; s < 3; s++)
#pragma unroll
        for (int n = 0; n < 2; n++) {
            float pa0 = (s < 2) ? pp[4 * s + n] : pp[8 + n];
            h0c[s][n] = elu1(pa0 + st.nc3 * rr[s * 2 + n] + st.nc2 * rr[6 + s * 2 + n]
                             + st.nc1 * rr[12 + s * 2 + n] + rr[18 + s * 2 + n]);
        }
    float h1c[3][2];
#pragma unroll
    for (int sc = 0; sc < 3; sc++)
#pragma unroll
        for (int n = 0; n < 2; n++) {
            float a = ((sc < 2) ? pp[4 * sc + 2 + n] : pp[10 + n]) + rr[24 + sc * 2 + n];
#pragma unroll
            for (int l = 0; l < 3; l++)
#pragma unroll
                for (int sp = 0; sp < 3; sp++)
                    a = fmaf(st.h0[l][sp][n], rr[32 + l * 18 + sp * 6 + sc * 2 + n], a);
#pragma unroll
            for (int sp = 0; sp < 3; sp++)
                a = fmaf(h0c[sp][n], rr[86 + sp * 6 + sc * 2 + n], a);  // 32+54
            h1c[sc][n] = elu1(a);
        }
    float mu = pp[12] + rr[128];
    float lv = pp[13] + rr[129];
#pragma unroll
    for (int l = 0; l < 3; l++)
#pragma unroll
        for (int sp = 0; sp < 3; sp++) {
            mu = fmaf(st.h1[l][sp][0], rr[104 + l * 6 + sp * 2 + 0], mu);
            lv = fmaf(st.h1[l][sp][1], rr[104 + l * 6 + sp * 2 + 1], lv);
        }
#pragma unroll
    for (int sp = 0; sp < 3; sp++) {
        mu = fmaf(h1c[sp][0], rr[122 + sp * 2 + 0], mu);   // 104+18
        lv = fmaf(h1c[sp][1], rr[122 + sp * 2 + 1], lv);
    }
    const float ls = 0.5f * lv;
    const float nc = (xi - mu) * __expf(-ls);
    st.lvsum += ls;
    if (lead) {
        *outp = nc;
        *(ull*)(pub + 0)  = packf2(nc, nc);
        *(ull*)(pub + 2)  = packf2(h0c[0][0], h0c[0][1]);
        *(ull*)(pub + 4)  = packf2(h0c[1][0], h0c[1][1]);
        *(ull*)(pub + 6)  = packf2(h1c[0][0], h1c[1][0]);
        *(ull*)(pub + 8)  = packf2(h1c[0][1], h1c[1][1]);
        *(ull*)(pub + 10) = packf2(h0c[2][0], h0c[2][1]);
        *(ull*)(pub + 12) = packf2(h1c[2][0], h1c[2][1]);
    }
    st.nc3 = st.nc2; st.nc2 = st.nc1; st.nc1 = nc;
#pragma unroll
    for (int s = 0; s < 3; s++)
#pragma unroll
        for (int n = 0; n < 2; n++) {
            st.h0[0][s][n] = st.h0[1][s][n]; st.h0[1][s][n] = st.h0[2][s][n]; st.h0[2][s][n] = h0c[s][n];
            st.h1[0][s][n] = st.h1[1][s][n]; st.h1[1][s][n] = st.h1[2][s][n]; st.h1[2][s][n] = h1c[s][n];
        }
}

// 128 CTAs, 544 threads. tid<512: wide; warp 16: combiner + record stager.
__global__ __launch_bounds__(544, 1) void made_kernel(
    const float* __restrict__ x, float* __restrict__ out)
{
    __shared__ __align__(16) float xs[256];
    __shared__ __align__(16) float pubB[64];     // 2 pair-buffers x 2 steps x 16
    __shared__ __align__(16) float parB[64];
    __shared__ __align__(16) float recbuf[2 * 272];

    const int tid = threadIdx.x;
    const int b = blockIdx.x;

    if (tid < 256) xs[tid] = x[b * DD + tid];
    if (tid < 128) { pubB[tid & 63] = 0.f; parB[tid & 63] = 0.f; }
    __syncthreads();

    float* const outb = out + b * DD;

    if (tid < 512) {
        // ================= WIDE =================
        const int u = tid;
        const int du = degf(u);
        const int su = u - Pof(du - 1);
        const int onet = (tid >> 8) & 1;
        const int ocol = tid & 255;
        const int pubRA = (du - 2) >> 1;    // publish pair; <1 => never (handled by zeros)
        const int pubRO = (ocol - 2) >> 1;
        const int off = (su < 2) ? (su << 2) : 8;
        const int qA = du & 1, qO = ocol & 1;

        ull A0 = 0, A1 = 0, AO = 0;
        float aoutC = 0.f;

        const ulonglong2* wA = g_wA + u;
        const ull* wA2 = g_wA2 + u;
        const ull* wO = g_wO + u;
        ulonglong2 Wa1r, Wa2r; ull Wa21, Wa22, Wo1r = 0, Wo2r = 0;
        Wa1r = make_ulonglong2(0, 0); Wa2r = make_ulonglong2(0, 0); Wa21 = 0; Wa22 = 0;
        if (pubRA >= 1) { Wa1r = wA[512];  Wa21 = wA2[512];  Wa2r = wA[1024]; Wa22 = wA2[1024]; }
        if (pubRO >= 1) { Wo1r = wO[512];  Wo2r = wO[1024]; }
        const ull w3p2 = g_w3p[u], w3p3 = g_w3p[512 + u];
        const float w3o2 = g_w3o[u], w3o3 = g_w3o[512 + u];

        BAR_ARRIVE(BPARP0 + 0);   // prime: par pair 0 (steps 0,1) zeros
        BAR_ARRIVE(BPARP0 + 1);   // prime: par pair 1 (steps 2,3) zeros

#pragma unroll 1
        for (int r = 1; r < 128; r++) {
            BAR_SYNC(BPUBP0 + ((r - 1) & 1));
            const float* pbE = pubB + (((2 * r - 2) & 3) << 4);   // pub(2r-2)
            const float* pbO = pubB + (((2 * r - 1) & 3) << 4);   // pub(2r-1)
            if (r <= pubRA) {
                // j = 2r-1 consumes pbE with row (2r-1)
                ffma2(A0, *(const ull*)(pbE + 0), Wa1r.x);
                ffma2(A1, *(const ull*)(pbE + 2), Wa1r.y);
                ffma2(A1, *(const ull*)(pbE + 4), Wa21);
                if (r == 2) ffma2(A1, *(const ull*)(pbE + 10), w3p3);   // j==3
                // j = 2r consumes pbO with row (2r)
                ffma2(A0, *(const ull*)(pbO + 0), Wa2r.x);
                ffma2(A1, *(const ull*)(pbO + 2), Wa2r.y);
                ffma2(A1, *(const ull*)(pbO + 4), Wa22);
                if (r == 1) ffma2(A1, *(const ull*)(pbO + 10), w3p2);   // j==2
                if (r == pubRA) {
                    float* pw = parB + (((r + 1) & 1) << 5) + (qA << 4) + off;
                    *(ull*)(pw + 0) = A0; *(ull*)(pw + 2) = A1;
                }
            }
            if (r <= pubRO) {
                ffma2(AO, *(const ull*)(pbE + 6 + 2 * onet), Wo1r);
                if (r == 2) aoutC = fmaf(pbE[12 + onet], w3o3, aoutC);
                ffma2(AO, *(const ull*)(pbO + 6 + 2 * onet), Wo2r);
                if (r == 1) aoutC = fmaf(pbO[12 + onet], w3o2, aoutC);
                if (r == pubRO)
                    parB[(((r + 1) & 1) << 5) + (qO << 4) + 12 + onet] = lof(AO) + hif(AO) + aoutC;
            }
            __threadfence_block();
            BAR_ARRIVE(BPARP0 + ((r + 1) & 1));
            if (r + 1 <= pubRA) {
                Wa1r = wA[(2 * r + 1) << 9]; Wa21 = wA2[(2 * r + 1) << 9];
                Wa2r = wA[(2 * r + 2) << 9]; Wa22 = wA2[(2 * r + 2) << 9];
            }
            if (r + 1 <= pubRO) {
                Wo1r = wO[(2 * r + 1) << 9]; Wo2r = wO[(2 * r + 2) << 9];
            }
        }
    } else {
        // ================= COMBINER (warp 16) =================
        const int lane = tid - 512;
        const bool lead = (lane == 0);
        // prime: records for pair 0
        {
            const float4* src = (const float4*)g_recU;
            float4* dst = (float4*)recbuf;
            for (int k = lane; k < 68; k += 32) dst[k] = src[k];
        }
        __syncwarp();
        CU st;
        st.nc1 = st.nc2 = st.nc3 = st.lvsum = 0.f;
#pragma unroll
        for (int l = 0; l < 3; l++)
#pragma unroll
            for (int s = 0; s < 3; s++)
#pragma unroll
                for (int n = 0; n < 2; n++) { st.h0[l][s][n] = 0.f; st.h1[l][s][n] = 0.f; }

#pragma unroll 1
        for (int r = 0; r < 128; r++) {
            BAR_SYNC(BPARP0 + (r & 1));
            // stage records for pair r+1 (latency hidden behind compute)
            if (r + 1 < 128) {
                const float4* src = (const float4*)(g_recU + (2 * (r + 1)) * 136);
                float4* dst = (float4*)(recbuf + ((r + 1) & 1) * 272);
                for (int k = lane; k < 68; k += 32) dst[k] = src[k];
            }
            const float* rb = recbuf + (r & 1) * 272;
            const float* pr = parB + ((r & 1) << 5);
            float* pu = pubB + ((r & 1) << 5);
            comb_u(pr,      pu,      rb,       xs[2 * r],     st, outb + 2 * r,     lead);
            comb_u(pr + 16, pu + 16, rb + 136, xs[2 * r + 1], st, outb + 2 * r + 1, lead);
            __threadfence_block();
            BAR_ARRIVE(BPUBP0 + (r & 1));
            __syncwarp();
        }
        if (lead) out[BB * DD + b] = st.lvsum;
    }
}

extern "C" void kernel_launch(void* const* d_in, const int* in_sizes, int n_in,
                              void* d_out, int out_size) {
    const float* xx   = (const float*)d_in[0];
    const float* muW0 = (const float*)d_in[1];
    const float* mub0 = (const float*)d_in[2];
    const float* muW1 = (const float*)d_in[3];
    const float* mub1 = (const float*)d_in[4];
    const float* muWo = (const float*)d_in[5];
    const float* mubo = (const float*)d_in[6];
    const float* lvW0 = (const float*)d_in[7];
    const float* lvb0 = (const float*)d_in[8];
    const float* lvW1 = (const float*)d_in[9];
    const float* lvb1 = (const float*)d_in[10];
    const float* lvWo = (const float*)d_in[11];
    const float* lvbo = (const float*)d_in[12];
    float* out = (float*)d_out;

    setup_kernel<<<512, 256>>>(muW0, muW1, muWo, mub0, mub1,
                               lvW0, lvW1, lvWo, lvb0, lvb1, mubo, lvbo);
    made_kernel<<<BB, 544>>>(xx, out);
}

// round 14
// speedup vs baseline: 1.8787x; 1.8787x over previous
#include <cuda_runtime.h>
#include <math.h>

#define DD 256
#define HH 512
#define BB 128
typedef unsigned long long ull;

__device__ __forceinline__ ull packf2(float lo, float hi) {
    return ((ull)__float_as_uint(hi) << 32) | (ull)__float_as_uint(lo);
}
__device__ __forceinline__ float lof(ull v) { return __uint_as_float((unsigned)v); }
__device__ __forceinline__ float hif(ull v) { return __uint_as_float((unsigned)(v >> 32)); }
__device__ __forceinline__ void ffma2(ull& d, ull a, ull b) {
    asm("fma.rn.f32x2 %0, %1, %2, %0;" : "+l"(d) : "l"(a), "l"(b));
}
#define BAR_SYNC(id)   asm volatile("bar.sync %0, 544;"   :: "r"(id) : "memory")
#define BAR_ARRIVE(id) asm volatile("bar.arrive %0, 544;" :: "r"(id) : "memory")
#define B_PAR0 1
#define B_PAR1 2
#define B_PUB0 3
#define B_PUB1 4

__device__ ulonglong2 g_wA[260 * 512];
__device__ ull g_wA2[260 * 512];
__device__ ull g_wO[260 * 512];
__device__ ull g_w3p[2 * 512];
__device__ float g_w3o[2 * 512];
__device__ float g_recS[256 * 40];
__device__ float g_recW[4 * 68];

__device__ __forceinline__ int permf(int p) {
    if (p < 3) return (p == 0) ? 0 : ((p == 1) ? 255 : 510);
    if (p < 6) { int q = p - 3; return (q == 0) ? 1 : ((q == 1) ? 256 : 511); }
    int d = 3 + ((p - 6) >> 1);
    return (((p - 6) & 1) == 0) ? (d - 1) : (d + 254);
}
__device__ __forceinline__ int degf(int p) {
    if (p < 3) return 1;
    if (p < 6) return 2;
    return 3 + ((p - 6) >> 1);
}
__device__ __forceinline__ int Pof(int k) {
    if (k <= 0) return 0;
    if (k == 1) return 3;
    int v = 2 * k + 2;
    return v > HH ? HH : v;
}
__device__ __forceinline__ float elu1(float a) {
    float e = __expf(a) - 1.f;
    return a > 0.f ? a : e;
}

__global__ void setup_kernel(
    const float* __restrict__ W0m, const float* __restrict__ W1m, const float* __restrict__ Wom,
    const float* __restrict__ b0m, const float* __restrict__ b1m,
    const float* __restrict__ W0l, const float* __restrict__ W1l, const float* __restrict__ Wol,
    const float* __restrict__ b0l, const float* __restrict__ b1l,
    const float* __restrict__ bom, const float* __restrict__ bol)
{
    int tid = blockIdx.x * blockDim.x + threadIdx.x;
    int stride = gridDim.x * blockDim.x;

    for (int idx = tid; idx < 256 * 512; idx += stride) {
        int i = idx >> 9, u = idx & 511;
        int du = degf(u), ou = permf(u);
        int onet = u >> 8, ocol = u & 255;
        const float* Wo = onet ? Wol : Wom;

        int w0row = i - 1 < 0 ? 0 : i - 1;
        float m0 = (du >= w0row + 1) ? 1.f : 0.f;
        float w0mu = m0 * W0m[ou * DD + w0row];
        float w0lv = m0 * W0l[ou * DD + w0row];

        int pB = Pof(i - 2);
        float w1s[2][2], wos[2];
#pragma unroll
        for (int s = 0; s < 2; s++) {
            int p = pB + s; if (p > HH - 1) p = HH - 1;
            int op = permf(p), dp = degf(p);
            float m1 = (du >= dp) ? 1.f : 0.f;
            w1s[s][0] = m1 * W1m[ou * HH + op];
            w1s[s][1] = m1 * W1l[ou * HH + op];
            float mo = (ocol >= dp) ? 1.f : 0.f;
            wos[s] = mo * Wo[ocol * HH + op];
        }
        g_wA[i * 512 + u] = make_ulonglong2(packf2(w0mu, w0lv), packf2(w1s[0][0], w1s[0][1]));
        g_wA2[i * 512 + u] = packf2(w1s[1][0], w1s[1][1]);
        g_wO[i * 512 + u] = packf2(wos[0], wos[1]);
    }
    for (int idx = tid; idx < 1024; idx += stride) {
        int j = idx >> 9, u = idx & 511;
        int du = degf(u), ou = permf(u);
        int onet = u >> 8, ocol = u & 255;
        const float* Wo = onet ? Wol : Wom;
        int p = (j == 0) ? 2 : 5;
        int op = permf(p), dp = degf(p);
        float m1 = (du >= dp) ? 1.f : 0.f;
        float mo = (ocol >= dp) ? 1.f : 0.f;
        g_w3p[idx] = packf2(m1 * W1m[ou * HH + op], m1 * W1l[ou * HH + op]);
        g_w3o[idx] = mo * Wo[ocol * HH + op];
    }
    for (int i = tid; i < 256; i += stride) {
        int cB = Pof(i - 1), cc = Pof(i) - cB;
        int pB = Pof(i - 2), cp = Pof(i - 1) - pB;
        {
            float* r = g_recS + i * 40;
            for (int k = 0; k < 40; k++) r[k] = 0.f;
            int c2 = cc < 2 ? cc : 2, p2 = cp < 2 ? cp : 2;
            for (int s = 0; s < c2; s++) {
                int p = permf(cB + s);
                if (i >= 1) { r[0 + 2 * s] = W0m[p * DD + (i - 1)]; r[1 + 2 * s] = W0l[p * DD + (i - 1)]; }
                r[4 + 2 * s] = b0m[p];  r[5 + 2 * s] = b0l[p];
                r[8 + 2 * s] = b1m[p];  r[9 + 2 * s] = b1l[p];
                r[32 + 2 * s] = Wom[i * HH + p]; r[33 + 2 * s] = Wol[i * HH + p];
            }
            for (int sp = 0; sp < p2; sp++) {
                int pp = permf(pB + sp);
                r[28 + 2 * sp] = Wom[i * HH + pp]; r[29 + 2 * sp] = Wol[i * HH + pp];
                for (int sc = 0; sc < c2; sc++) {
                    int g = permf(cB + sc);
                    r[12 + sp * 4 + 2 * sc] = W1m[g * HH + pp];
                    r[13 + sp * 4 + 2 * sc] = W1l[g * HH + pp];
                }
            }
            for (int sp = 0; sp < c2; sp++)
                for (int sc = 0; sc < c2; sc++) {
                    int pp = permf(cB + sp), g = permf(cB + sc);
                    r[20 + sp * 4 + 2 * sc] = W1m[g * HH + pp];
                    r[21 + sp * 4 + 2 * sc] = W1l[g * HH + pp];
                }
            r[36] = bom[i]; r[37] = bol[i];
        }
        if (i < 4) {
            float* r = g_recW + i * 68;
            for (int k = 0; k < 68; k++) r[k] = 0.f;
            for (int s = 0; s < cc; s++) {
                int p = permf(cB + s);
                if (i >= 1) { r[0 + 2 * s] = W0m[p * DD + (i - 1)]; r[1 + 2 * s] = W0l[p * DD + (i - 1)]; }
                r[6 + 2 * s] = b0m[p];  r[7 + 2 * s] = b0l[p];
                r[12 + 2 * s] = b1m[p]; r[13 + 2 * s] = b1l[p];
                r[60 + 2 * s] = Wom[i * HH + p]; r[61 + 2 * s] = Wol[i * HH + p];
            }
            for (int sp = 0; sp < cp; sp++) {
                int pp = permf(pB + sp);
                r[54 + 2 * sp] = Wom[i * HH + pp]; r[55 + 2 * sp] = Wol[i * HH + pp];
                for (int sc = 0; sc < cc; sc++) {
                    int g = permf(cB + sc);
                    r[18 + sp * 6 + 2 * sc] = W1m[g * HH + pp];
                    r[19 + sp * 6 + 2 * sc] = W1l[g * HH + pp];
                }
            }
            for (int sp = 0; sp < cc; sp++)
                for (int sc = 0; sc < cc; sc++) {
                    int pp = permf(cB + sp), g = permf(cB + sc);
                    r[36 + sp * 6 + 2 * sc] = W1m[g * HH + pp];
                    r[37 + sp * 6 + 2 * sc] = W1l[g * HH + pp];
                }
            r[66] = bom[i]; r[67] = bol[i];
        }
    }
}

#define OFF_RECS 0
#define OFF_RECW 10240
#define OFF_XS   10512
#define OFF_PUB  10768
#define OFF_PAR  10800
#define SM_FLOATS 10832

// 2-lane net-split combiner step. lane n handles net n entirely; one shfl.xor at the end.
__device__ __forceinline__ void comb_lane(
    int i, const float* __restrict__ pr, float* __restrict__ pu,
    const float* __restrict__ SMbase, int n,
    float& nc, float& h0p0, float& h0p1, float& h0p2,
    float& h1p0, float& h1p1, float& h1p2,
    float& lvsum, float* __restrict__ outp)
{
    const float xi = SMbase[OFF_XS + i];
    float h0c0, h0c1, h0c2 = 0.f, h1c0, h1c1, h1c2 = 0.f;
    float m;
    if (i >= 4) {
        const float* r = SMbase + OFF_RECS + i * 40 + n;
        h0c0 = elu1(pr[0 + n] + nc * r[0] + r[4]);
        h0c1 = elu1(pr[4 + n] + nc * r[2] + r[6]);
        float a0 = pr[2 + n] + r[8];
        a0 = fmaf(h0p0, r[12], a0); a0 = fmaf(h0p1, r[16], a0);
        a0 = fmaf(h0c0, r[20], a0); a0 = fmaf(h0c1, r[24], a0);
        h1c0 = elu1(a0);
        float a1 = pr[6 + n] + r[10];
        a1 = fmaf(h0p0, r[14], a1); a1 = fmaf(h0p1, r[18], a1);
        a1 = fmaf(h0c0, r[22], a1); a1 = fmaf(h0c1, r[26], a1);
        h1c1 = elu1(a1);
        m = pr[12 + n] + r[36];
        m = fmaf(h1p0, r[28], m); m = fmaf(h1p1, r[30], m);
        m = fmaf(h1c0, r[32], m); m = fmaf(h1c1, r[34], m);
    } else {
        const float* r = SMbase + OFF_RECW + i * 68 + n;
        h0c0 = elu1(pr[0 + n] + nc * r[0] + r[6]);
        h0c1 = elu1(pr[4 + n] + nc * r[2] + r[8]);
        h0c2 = elu1(pr[8 + n] + nc * r[4] + r[10]);
        float a0 = pr[2 + n] + r[12];
        a0 = fmaf(h0p0, r[18], a0); a0 = fmaf(h0p1, r[24], a0); a0 = fmaf(h0p2, r[30], a0);
        a0 = fmaf(h0c0, r[36], a0); a0 = fmaf(h0c1, r[42], a0); a0 = fmaf(h0c2, r[48], a0);
        h1c0 = elu1(a0);
        float a1 = pr[6 + n] + r[14];
        a1 = fmaf(h0p0, r[20], a1); a1 = fmaf(h0p1, r[26], a1); a1 = fmaf(h0p2, r[32], a1);
        a1 = fmaf(h0c0, r[38], a1); a1 = fmaf(h0c1, r[44], a1); a1 = fmaf(h0c2, r[50], a1);
        h1c1 = elu1(a1);
        float a2 = pr[10 + n] + r[16];
        a2 = fmaf(h0p0, r[22], a2); a2 = fmaf(h0p1, r[28], a2); a2 = fmaf(h0p2, r[34], a2);
        a2 = fmaf(h0c0, r[40], a2); a2 = fmaf(h0c1, r[46], a2); a2 = fmaf(h0c2, r[52], a2);
        h1c2 = elu1(a2);
        m = pr[12 + n] + r[66];
        m = fmaf(h1p0, r[54], m); m = fmaf(h1p1, r[56], m); m = fmaf(h1p2, r[58], m);
        m = fmaf(h1c0, r[60], m); m = fmaf(h1c1, r[62], m); m = fmaf(h1c2, r[64], m);
    }
    // swap mu <-> lv between the two lanes in one shuffle
    const float other = __shfl_xor_sync(0x3u, m, 1);
    const float mu = (n == 0) ? m : other;
    const float lv = (n == 0) ? other : m;
    const float ls = 0.5f * lv;
    const float ncn = (xi - mu) * __expf(-ls);   // redundant, deterministic on both lanes
    nc = ncn;
    if (n) lvsum += ls;
    else   *outp = ncn;
    pu[n] = ncn;
    pu[2 + n] = h0c0; pu[4 + n] = h0c1;
    pu[6 + 2 * n] = h1c0; pu[7 + 2 * n] = h1c1;
    if (i < 4) { pu[10 + n] = h0c2; pu[12 + n] = h1c2; }
    h0p0 = h0c0; h0p1 = h0c1; h0p2 = h0c2;
    h1p0 = h1c0; h1p1 = h1c1; h1p2 = h1c2;
}

__device__ __forceinline__ void wide_step(
    int i, const float* __restrict__ pb, const float* __restrict__ pbh,
    const float* __restrict__ pb12,
    ulonglong2 Wa, ull Wa2, ull Wo,
    ull& A0, ull& A1, ull& AO, float& aoutC,
    int pubA, int pubO, float* __restrict__ pwA, float* __restrict__ pwO,
    ull w3p2, ull w3p3, float w3o2, float w3o3)
{
    if (i <= pubA) {
        const ull nc2  = *(const ull*)(pb + 0);
        const ull h0s0 = *(const ull*)(pb + 2);
        const ull h0s1 = *(const ull*)(pb + 4);
        ffma2(A0, nc2, Wa.x);
        ffma2(A1, h0s0, Wa.y);
        ffma2(A1, h0s1, Wa2);
        if ((unsigned)(i - 2) < 2u) {
            const ull h0s2 = *(const ull*)(pb + 10);
            ffma2(A1, h0s2, (i == 2) ? w3p2 : w3p3);
        }
        if (i == pubA) { *(ull*)(pwA + 0) = A0; *(ull*)(pwA + 2) = A1; }
    }
    if (i <= pubO) {
        const ull h1p = *(const ull*)pbh;
        ffma2(AO, h1p, Wo);
        if ((unsigned)(i - 2) < 2u)
            aoutC = fmaf(*pb12, (i == 2) ? w3o2 : w3o3, aoutC);
        if (i == pubO) *pwO = lof(AO) + hif(AO) + aoutC;
    }
}

__global__ __launch_bounds__(544, 1) void made_kernel(
    const float* __restrict__ x, float* __restrict__ out)
{
    __shared__ __align__(16) float SM[SM_FLOATS];

    const int tid = threadIdx.x;
    const int b = blockIdx.x;

    {
        const float4* src = (const float4*)g_recS;
        float4* dst = (float4*)(SM + OFF_RECS);
        for (int k = tid; k < (256 * 40) / 4; k += 544) dst[k] = src[k];
        for (int k = tid; k < 4 * 68; k += 544) SM[OFF_RECW + k] = g_recW[k];
        if (tid < 256) SM[OFF_XS + tid] = x[b * DD + tid];
        for (int k = tid; k < 64; k += 544) SM[OFF_PUB + k] = 0.f;
    }
    __syncthreads();

    float* const pub0 = SM + OFF_PUB;
    float* const pub1 = SM + OFF_PUB + 16;
    float* const par0 = SM + OFF_PAR;
    float* const par1 = SM + OFF_PAR + 16;
    float* const outb = out + b * DD;

    if (tid < 512) {
        // ---- wide warps ----
        const int u = tid;
        const int du = degf(u);
        const int su = u - Pof(du - 1);
        const int onet = (tid >> 8) & 1;
        const int ocol = tid & 255;
        const int pubA = du - 1;
        const int pubO = ocol - 1;
        const int off = (su < 2) ? (su << 2) : 8;

        float* const pwA0 = par0 + off;
        float* const pwA1 = par1 + off;
        float* const pwO0 = par0 + 12 + onet;
        float* const pwO1 = par1 + 12 + onet;
        const float* const pbh0 = pub0 + 6 + 2 * onet;
        const float* const pbh1 = pub1 + 6 + 2 * onet;
        const float* const pb120 = pub0 + 12 + onet;
        const float* const pb121 = pub1 + 12 + onet;

        ull A0 = 0, A1 = 0, AO = 0;
        float aoutC = 0.f;

        const ulonglong2* wA = g_wA + u;
        const ull* wA2 = g_wA2 + u;
        const ull* wO = g_wO + u;
        ulonglong2 Wa0 = wA[0],   Wa1 = wA[512];
        ull Wa20 = wA2[0], Wa21 = wA2[512];
        ull Wo0 = wO[0],   Wo1 = wO[512];
        const ull w3p2 = g_w3p[u], w3p3 = g_w3p[512 + u];
        const float w3o2 = g_w3o[u], w3o3 = g_w3o[512 + u];

        BAR_ARRIVE(B_PAR0);

#pragma unroll 1
        for (int i = 0; i < DD; i += 2) {
            BAR_SYNC(B_PUB1);
            wide_step(i, pub1, pbh1, pb121, Wa0, Wa20, Wo0, A0, A1, AO, aoutC,
                      pubA, pubO, pwA1, pwO1, w3p2, w3p3, w3o2, w3o3);
            __threadfence_block();
            BAR_ARRIVE(B_PAR1);
            if (i + 2 <= pubA) { Wa0 = wA[(i + 2) << 9]; Wa20 = wA2[(i + 2) << 9]; }
            if (i + 2 <= pubO) { Wo0 = wO[(i + 2) << 9]; }
            BAR_SYNC(B_PUB0);
            wide_step(i + 1, pub0, pbh0, pb120, Wa1, Wa21, Wo1, A0, A1, AO, aoutC,
                      pubA, pubO, pwA0, pwO0, w3p2, w3p3, w3o2, w3o3);
            __threadfence_block();
            BAR_ARRIVE(B_PAR0);
            if (i + 3 <= pubA) { Wa1 = wA[(i + 3) << 9]; Wa21 = wA2[(i + 3) << 9]; }
            if (i + 3 <= pubO) { Wo1 = wO[(i + 3) << 9]; }
        }
    } else {
        // ---- combiner warp (warp 16): lanes 0,1 compute (net-split) ----
        const int ln = tid - 512;
        const int n = ln & 1;
        const bool act = (ln < 2);
        float h0p0 = 0.f, h0p1 = 0.f, h0p2 = 0.f;
        float h1p0 = 0.f, h1p1 = 0.f, h1p2 = 0.f;
        float nc = 0.f, lvsum = 0.f;

        BAR_ARRIVE(B_PUB1);

#pragma unroll 1
        for (int i = 0; i < DD; i += 2) {
            BAR_SYNC(B_PAR0);
            if (act)
                comb_lane(i, par0, pub0, SM, n, nc, h0p0, h0p1, h0p2,
                          h1p0, h1p1, h1p2, lvsum, outb + i);
            __threadfence_block();
            BAR_ARRIVE(B_PUB0);
            BAR_SYNC(B_PAR1);
            if (act)
                comb_lane(i + 1, par1, pub1, SM, n, nc, h0p0, h0p1, h0p2,
                          h1p0, h1p1, h1p2, lvsum, outb + i + 1);
            __threadfence_block();
            BAR_ARRIVE(B_PUB1);
        }
        if (ln == 1) out[BB * DD + b] = lvsum;
    }
}

extern "C" void kernel_launch(void* const* d_in, const int* in_sizes, int n_in,
                              void* d_out, int out_size) {
    const float* xx   = (const float*)d_in[0];
    const float* muW0 = (const float*)d_in[1];
    const float* mub0 = (const float*)d_in[2];
    const float* muW1 = (const float*)d_in[3];
    const float* mub1 = (const float*)d_in[4];
    const float* muWo = (const float*)d_in[5];
    const float* mubo = (const float*)d_in[6];
    const float* lvW0 = (const float*)d_in[7];
    const float* lvb0 = (const float*)d_in[8];
    const float* lvW1 = (const float*)d_in[9];
    const float* lvb1 = (const float*)d_in[10];
    const float* lvWo = (const float*)d_in[11];
    const float* lvbo = (const float*)d_in[12];
    float* out = (float*)d_out;

    setup_kernel<<<512, 256>>>(muW0, muW1, muWo, mub0, mub1,
                               lvW0, lvW1, lvWo, lvb0, lvb1, mubo, lvbo);
    made_kernel<<<BB, 544>>>(xx, out);
}

// round 15
// speedup vs baseline: 1.8851x; 1.0034x over previous
#include <cuda_runtime.h>
#include <math.h>

#define DD 256
#define HH 512
#define BB 128
typedef unsigned long long ull;

__device__ __forceinline__ ull packf2(float lo, float hi) {
    return ((ull)__float_as_uint(hi) << 32) | (ull)__float_as_uint(lo);
}
__device__ __forceinline__ float lof(ull v) { return __uint_as_float((unsigned)v); }
__device__ __forceinline__ float hif(ull v) { return __uint_as_float((unsigned)(v >> 32)); }
__device__ __forceinline__ void ffma2(ull& d, ull a, ull b) {
    asm("fma.rn.f32x2 %0, %1, %2, %0;" : "+l"(d) : "l"(a), "l"(b));
}
__device__ __forceinline__ unsigned smem_u32(const void* p) {
    return (unsigned)__cvta_generic_to_shared(p);
}
#define MBAR_INIT(addr, cnt) \
    asm volatile("mbarrier.init.shared.b64 [%0], %1;" :: "r"(addr), "r"(cnt) : "memory")
#define MBAR_ARRIVE(addr) \
    asm volatile("mbarrier.arrive.shared.b64 _, [%0];" :: "r"(addr) : "memory")
#define MBAR_WAIT(addr, parity) do {                                          \
    unsigned _m = (addr), _p = (parity), _done;                               \
    asm volatile("{\n\t.reg .pred p;\n\t"                                     \
        "mbarrier.try_wait.parity.acquire.cta.shared::cta.b64 p, [%1], %2;\n\t" \
        "selp.b32 %0, 1, 0, p;\n\t}"                                          \
        : "=r"(_done) : "r"(_m), "r"(_p) : "memory");                         \
    if (!_done) {                                                             \
        asm volatile("{\n\t.reg .pred P1;\n\t"                                \
            "WL_%=:\n\t"                                                      \
            "mbarrier.try_wait.parity.acquire.cta.shared::cta.b64 P1, [%0], %1, 0x989680;\n\t" \
            "@P1 bra.uni WD_%=;\n\t"                                          \
            "bra.uni WL_%=;\n\t"                                              \
            "WD_%=:\n\t}"                                                     \
            :: "r"(_m), "r"(_p) : "memory");                                  \
    }                                                                         \
} while (0)

__device__ ulonglong2 g_wA[260 * 512];
__device__ ull g_wA2[260 * 512];
__device__ ull g_wO[260 * 512];
__device__ ull g_w3p[2 * 512];
__device__ float g_w3o[2 * 512];
__device__ float g_recS[256 * 40];
__device__ float g_recW[4 * 68];

__device__ __forceinline__ int permf(int p) {
    if (p < 3) return (p == 0) ? 0 : ((p == 1) ? 255 : 510);
    if (p < 6) { int q = p - 3; return (q == 0) ? 1 : ((q == 1) ? 256 : 511); }
    int d = 3 + ((p - 6) >> 1);
    return (((p - 6) & 1) == 0) ? (d - 1) : (d + 254);
}
__device__ __forceinline__ int degf(int p) {
    if (p < 3) return 1;
    if (p < 6) return 2;
    return 3 + ((p - 6) >> 1);
}
__device__ __forceinline__ int Pof(int k) {
    if (k <= 0) return 0;
    if (k == 1) return 3;
    int v = 2 * k + 2;
    return v > HH ? HH : v;
}
__device__ __forceinline__ float elu1(float a) {
    float e = __expf(a) - 1.f;
    return a > 0.f ? a : e;
}

__global__ void setup_kernel(
    const float* __restrict__ W0m, const float* __restrict__ W1m, const float* __restrict__ Wom,
    const float* __restrict__ b0m, const float* __restrict__ b1m,
    const float* __restrict__ W0l, const float* __restrict__ W1l, const float* __restrict__ Wol,
    const float* __restrict__ b0l, const float* __restrict__ b1l,
    const float* __restrict__ bom, const float* __restrict__ bol)
{
    int tid = blockIdx.x * blockDim.x + threadIdx.x;
    int stride = gridDim.x * blockDim.x;

    for (int idx = tid; idx < 256 * 512; idx += stride) {
        int i = idx >> 9, u = idx & 511;
        int du = degf(u), ou = permf(u);
        int onet = u >> 8, ocol = u & 255;
        const float* Wo = onet ? Wol : Wom;

        int w0row = i - 1 < 0 ? 0 : i - 1;
        float m0 = (du >= w0row + 1) ? 1.f : 0.f;
        float w0mu = m0 * W0m[ou * DD + w0row];
        float w0lv = m0 * W0l[ou * DD + w0row];

        int pB = Pof(i - 2);
        float w1s[2][2], wos[2];
#pragma unroll
        for (int s = 0; s < 2; s++) {
            int p = pB + s; if (p > HH - 1) p = HH - 1;
            int op = permf(p), dp = degf(p);
            float m1 = (du >= dp) ? 1.f : 0.f;
            w1s[s][0] = m1 * W1m[ou * HH + op];
            w1s[s][1] = m1 * W1l[ou * HH + op];
            float mo = (ocol >= dp) ? 1.f : 0.f;
            wos[s] = mo * Wo[ocol * HH + op];
        }
        g_wA[i * 512 + u] = make_ulonglong2(packf2(w0mu, w0lv), packf2(w1s[0][0], w1s[0][1]));
        g_wA2[i * 512 + u] = packf2(w1s[1][0], w1s[1][1]);
        g_wO[i * 512 + u] = packf2(wos[0], wos[1]);
    }
    for (int idx = tid; idx < 1024; idx += stride) {
        int j = idx >> 9, u = idx & 511;
        int du = degf(u), ou = permf(u);
        int onet = u >> 8, ocol = u & 255;
        const float* Wo = onet ? Wol : Wom;
        int p = (j == 0) ? 2 : 5;
        int op = permf(p), dp = degf(p);
        float m1 = (du >= dp) ? 1.f : 0.f;
        float mo = (ocol >= dp) ? 1.f : 0.f;
        g_w3p[idx] = packf2(m1 * W1m[ou * HH + op], m1 * W1l[ou * HH + op]);
        g_w3o[idx] = mo * Wo[ocol * HH + op];
    }
    for (int i = tid; i < 256; i += stride) {
        int cB = Pof(i - 1), cc = Pof(i) - cB;
        int pB = Pof(i - 2), cp = Pof(i - 1) - pB;
        {
            float* r = g_recS + i * 40;
            for (int k = 0; k < 40; k++) r[k] = 0.f;
            int c2 = cc < 2 ? cc : 2, p2 = cp < 2 ? cp : 2;
            for (int s = 0; s < c2; s++) {
                int p = permf(cB + s);
                if (i >= 1) { r[0 + 2 * s] = W0m[p * DD + (i - 1)]; r[1 + 2 * s] = W0l[p * DD + (i - 1)]; }
                r[4 + 2 * s] = b0m[p];  r[5 + 2 * s] = b0l[p];
                r[8 + 2 * s] = b1m[p];  r[9 + 2 * s] = b1l[p];
                r[32 + 2 * s] = Wom[i * HH + p]; r[33 + 2 * s] = Wol[i * HH + p];
            }
            for (int sp = 0; sp < p2; sp++) {
                int pp = permf(pB + sp);
                r[28 + 2 * sp] = Wom[i * HH + pp]; r[29 + 2 * sp] = Wol[i * HH + pp];
                for (int sc = 0; sc < c2; sc++) {
                    int g = permf(cB + sc);
                    r[12 + sp * 4 + 2 * sc] = W1m[g * HH + pp];
                    r[13 + sp * 4 + 2 * sc] = W1l[g * HH + pp];
                }
            }
            for (int sp = 0; sp < c2; sp++)
                for (int sc = 0; sc < c2; sc++) {
                    int pp = permf(cB + sp), g = permf(cB + sc);
                    r[20 + sp * 4 + 2 * sc] = W1m[g * HH + pp];
                    r[21 + sp * 4 + 2 * sc] = W1l[g * HH + pp];
                }
            r[36] = bom[i]; r[37] = bol[i];
        }
        if (i < 4) {
            float* r = g_recW + i * 68;
            for (int k = 0; k < 68; k++) r[k] = 0.f;
            for (int s = 0; s < cc; s++) {
                int p = permf(cB + s);
                if (i >= 1) { r[0 + 2 * s] = W0m[p * DD + (i - 1)]; r[1 + 2 * s] = W0l[p * DD + (i - 1)]; }
                r[6 + 2 * s] = b0m[p];  r[7 + 2 * s] = b0l[p];
                r[12 + 2 * s] = b1m[p]; r[13 + 2 * s] = b1l[p];
                r[60 + 2 * s] = Wom[i * HH + p]; r[61 + 2 * s] = Wol[i * HH + p];
            }
            for (int sp = 0; sp < cp; sp++) {
                int pp = permf(pB + sp);
                r[54 + 2 * sp] = Wom[i * HH + pp]; r[55 + 2 * sp] = Wol[i * HH + pp];
                for (int sc = 0; sc < cc; sc++) {
                    int g = permf(cB + sc);
                    r[18 + sp * 6 + 2 * sc] = W1m[g * HH + pp];
                    r[19 + sp * 6 + 2 * sc] = W1l[g * HH + pp];
                }
            }
            for (int sp = 0; sp < cc; sp++)
                for (int sc = 0; sc < cc; sc++) {
                    int pp = permf(cB + sp), g = permf(cB + sc);
                    r[36 + sp * 6 + 2 * sc] = W1m[g * HH + pp];
                    r[37 + sp * 6 + 2 * sc] = W1l[g * HH + pp];
                }
            r[66] = bom[i]; r[67] = bol[i];
        }
    }
}

#define OFF_RECS 0
#define OFF_RECW 10240
#define OFF_XS   10512
#define OFF_PUB  10768
#define OFF_PAR  10800
#define OFF_MBAR 10832   // 4 mbarriers (u64) => 8 floats
#define SM_FLOATS 10840

// 2-lane net-split combiner step (identical math to R14)
__device__ __forceinline__ void comb_lane(
    int i, const float* __restrict__ pr, float* __restrict__ pu,
    const float* __restrict__ SMbase, int n,
    float& nc, float& h0p0, float& h0p1, float& h0p2,
    float& h1p0, float& h1p1, float& h1p2,
    float& lvsum, float& ncout)
{
    const float xi = SMbase[OFF_XS + i];
    float h0c0, h0c1, h0c2 = 0.f, h1c0, h1c1, h1c2 = 0.f;
    float m;
    if (i >= 4) {
        const float* r = SMbase + OFF_RECS + i * 40 + n;
        h0c0 = elu1(pr[0 + n] + nc * r[0] + r[4]);
        h0c1 = elu1(pr[4 + n] + nc * r[2] + r[6]);
        float a0 = pr[2 + n] + r[8];
        a0 = fmaf(h0p0, r[12], a0); a0 = fmaf(h0p1, r[16], a0);
        a0 = fmaf(h0c0, r[20], a0); a0 = fmaf(h0c1, r[24], a0);
        h1c0 = elu1(a0);
        float a1 = pr[6 + n] + r[10];
        a1 = fmaf(h0p0, r[14], a1); a1 = fmaf(h0p1, r[18], a1);
        a1 = fmaf(h0c0, r[22], a1); a1 = fmaf(h0c1, r[26], a1);
        h1c1 = elu1(a1);
        m = pr[12 + n] + r[36];
        m = fmaf(h1p0, r[28], m); m = fmaf(h1p1, r[30], m);
        m = fmaf(h1c0, r[32], m); m = fmaf(h1c1, r[34], m);
    } else {
        const float* r = SMbase + OFF_RECW + i * 68 + n;
        h0c0 = elu1(pr[0 + n] + nc * r[0] + r[6]);
        h0c1 = elu1(pr[4 + n] + nc * r[2] + r[8]);
        h0c2 = elu1(pr[8 + n] + nc * r[4] + r[10]);
        float a0 = pr[2 + n] + r[12];
        a0 = fmaf(h0p0, r[18], a0); a0 = fmaf(h0p1, r[24], a0); a0 = fmaf(h0p2, r[30], a0);
        a0 = fmaf(h0c0, r[36], a0); a0 = fmaf(h0c1, r[42], a0); a0 = fmaf(h0c2, r[48], a0);
        h1c0 = elu1(a0);
        float a1 = pr[6 + n] + r[14];
        a1 = fmaf(h0p0, r[20], a1); a1 = fmaf(h0p1, r[26], a1); a1 = fmaf(h0p2, r[32], a1);
        a1 = fmaf(h0c0, r[38], a1); a1 = fmaf(h0c1, r[44], a1); a1 = fmaf(h0c2, r[50], a1);
        h1c1 = elu1(a1);
        float a2 = pr[10 + n] + r[16];
        a2 = fmaf(h0p0, r[22], a2); a2 = fmaf(h0p1, r[28], a2); a2 = fmaf(h0p2, r[34], a2);
        a2 = fmaf(h0c0, r[40], a2); a2 = fmaf(h0c1, r[46], a2); a2 = fmaf(h0c2, r[52], a2);
        h1c2 = elu1(a2);
        m = pr[12 + n] + r[66];
        m = fmaf(h1p0, r[54], m); m = fmaf(h1p1, r[56], m); m = fmaf(h1p2, r[58], m);
        m = fmaf(h1c0, r[60], m); m = fmaf(h1c1, r[62], m); m = fmaf(h1c2, r[64], m);
    }
    const float other = __shfl_xor_sync(0x3u, m, 1);
    const float mu = (n == 0) ? m : other;
    const float lv = (n == 0) ? other : m;
    const float ls = 0.5f * lv;
    const float ncn = (xi - mu) * __expf(-ls);
    nc = ncn;
    if (n) lvsum += ls;
    ncout = ncn;
    pu[n] = ncn;
    pu[2 + n] = h0c0; pu[4 + n] = h0c1;
    pu[6 + 2 * n] = h1c0; pu[7 + 2 * n] = h1c1;
    if (i < 4) { pu[10 + n] = h0c2; pu[12 + n] = h1c2; }
    h0p0 = h0c0; h0p1 = h0c1; h0p2 = h0c2;
    h1p0 = h1c0; h1p1 = h1c1; h1p2 = h1c2;
}

__device__ __forceinline__ void wide_step(
    int i, const float* __restrict__ pb, const float* __restrict__ pbh,
    const float* __restrict__ pb12,
    ulonglong2 Wa, ull Wa2, ull Wo,
    ull& A0, ull& A1, ull& AO, float& aoutC,
    int pubA, int pubO, float* __restrict__ pwA, float* __restrict__ pwO,
    ull w3p2, ull w3p3, float w3o2, float w3o3)
{
    if (i <= pubA) {
        const ull nc2  = *(const ull*)(pb + 0);
        const ull h0s0 = *(const ull*)(pb + 2);
        const ull h0s1 = *(const ull*)(pb + 4);
        ffma2(A0, nc2, Wa.x);
        ffma2(A1, h0s0, Wa.y);
        ffma2(A1, h0s1, Wa2);
        if ((unsigned)(i - 2) < 2u) {
            const ull h0s2 = *(const ull*)(pb + 10);
            ffma2(A1, h0s2, (i == 2) ? w3p2 : w3p3);
        }
        if (i == pubA) { *(ull*)(pwA + 0) = A0; *(ull*)(pwA + 2) = A1; }
    }
    if (i <= pubO) {
        const ull h1p = *(const ull*)pbh;
        ffma2(AO, h1p, Wo);
        if ((unsigned)(i - 2) < 2u)
            aoutC = fmaf(*pb12, (i == 2) ? w3o2 : w3o3, aoutC);
        if (i == pubO) *pwO = lof(AO) + hif(AO) + aoutC;
    }
}

__global__ __launch_bounds__(544, 1) void made_kernel(
    const float* __restrict__ x, float* __restrict__ out)
{
    __shared__ __align__(16) float SM[SM_FLOATS];

    const int tid = threadIdx.x;
    const int b = blockIdx.x;

    {
        const float4* src = (const float4*)g_recS;
        float4* dst = (float4*)(SM + OFF_RECS);
        for (int k = tid; k < (256 * 40) / 4; k += 544) dst[k] = src[k];
        for (int k = tid; k < 4 * 68; k += 544) SM[OFF_RECW + k] = g_recW[k];
        if (tid < 256) SM[OFF_XS + tid] = x[b * DD + tid];
        for (int k = tid; k < 64; k += 544) SM[OFF_PUB + k] = 0.f;
    }
    // mbarriers: [0]=PAR0 [1]=PAR1 [2]=PUB0 [3]=PUB1
    const unsigned mb = smem_u32(SM + OFF_MBAR);
    const unsigned mPAR0 = mb, mPAR1 = mb + 8, mPUB0 = mb + 16, mPUB1 = mb + 24;
    if (tid == 0) {
        MBAR_INIT(mPAR0, 16);
        MBAR_INIT(mPAR1, 16);
        MBAR_INIT(mPUB0, 1);
        MBAR_INIT(mPUB1, 1);
    }
    __syncthreads();

    float* const pub0 = SM + OFF_PUB;
    float* const pub1 = SM + OFF_PUB + 16;
    float* const par0 = SM + OFF_PAR;
    float* const par1 = SM + OFF_PAR + 16;
    float* const outb = out + b * DD;

    if (tid < 512) {
        // ---- wide warps ----
        const int u = tid;
        const int du = degf(u);
        const int su = u - Pof(du - 1);
        const int onet = (tid >> 8) & 1;
        const int ocol = tid & 255;
        const int pubA = du - 1;
        const int pubO = ocol - 1;
        const int off = (su < 2) ? (su << 2) : 8;
        const bool elect = ((tid & 31) == 0);

        float* const pwA0 = par0 + off;
        float* const pwA1 = par1 + off;
        float* const pwO0 = par0 + 12 + onet;
        float* const pwO1 = par1 + 12 + onet;
        const float* const pbh0 = pub0 + 6 + 2 * onet;
        const float* const pbh1 = pub1 + 6 + 2 * onet;
        const float* const pb120 = pub0 + 12 + onet;
        const float* const pb121 = pub1 + 12 + onet;

        ull A0 = 0, A1 = 0, AO = 0;
        float aoutC = 0.f;

        const ulonglong2* wA = g_wA + u;
        const ull* wA2 = g_wA2 + u;
        const ull* wO = g_wO + u;
        ulonglong2 Wa0 = wA[0],   Wa1 = wA[512];
        ull Wa20 = wA2[0], Wa21 = wA2[512];
        ull Wo0 = wO[0],   Wo1 = wO[512];
        const ull w3p2 = g_w3p[u], w3p3 = g_w3p[512 + u];
        const float w3o2 = g_w3o[u], w3o3 = g_w3o[512 + u];

        if (elect) MBAR_ARRIVE(mPAR0);   // prime par(0) = zeros

#pragma unroll 1
        for (int t = 0; t < 128; t++) {
            const unsigned ph = (unsigned)(t & 1);
            const int i = 2 * t;
            // even step i: consume pub(i-1) in pub1 buffer, publish par(i+1) in par1
            MBAR_WAIT(mPUB1, ph);
            wide_step(i, pub1, pbh1, pb121, Wa0, Wa20, Wo0, A0, A1, AO, aoutC,
                      pubA, pubO, pwA1, pwO1, w3p2, w3p3, w3o2, w3o3);
            __syncwarp();
            if (elect) MBAR_ARRIVE(mPAR1);
            if (i + 2 <= pubA) { Wa0 = wA[(i + 2) << 9]; Wa20 = wA2[(i + 2) << 9]; }
            if (i + 2 <= pubO) { Wo0 = wO[(i + 2) << 9]; }
            // odd step i+1: consume pub(i) in pub0, publish par(i+2) in par0
            MBAR_WAIT(mPUB0, ph);
            wide_step(i + 1, pub0, pbh0, pb120, Wa1, Wa21, Wo1, A0, A1, AO, aoutC,
                      pubA, pubO, pwA0, pwO0, w3p2, w3p3, w3o2, w3o3);
            __syncwarp();
            if (elect) MBAR_ARRIVE(mPAR0);
            if (i + 3 <= pubA) { Wa1 = wA[(i + 3) << 9]; Wa21 = wA2[(i + 3) << 9]; }
            if (i + 3 <= pubO) { Wo1 = wO[(i + 3) << 9]; }
        }
    } else {
        // ---- combiner warp (warp 16): lanes 0,1 compute (net-split) ----
        const int ln = tid - 512;
        if (ln >= 2) return;
        const int n = ln;
        float h0p0 = 0.f, h0p1 = 0.f, h0p2 = 0.f;
        float h1p0 = 0.f, h1p1 = 0.f, h1p2 = 0.f;
        float nc = 0.f, lvsum = 0.f, ncout;

        if (ln == 0) MBAR_ARRIVE(mPUB1);   // prime pub(-1) = zeros

#pragma unroll 1
        for (int t = 0; t < 128; t++) {
            const unsigned ph = (unsigned)(t & 1);
            const int i = 2 * t;
            MBAR_WAIT(mPAR0, ph);
            comb_lane(i, par0, pub0, SM, n, nc, h0p0, h0p1, h0p2,
                      h1p0, h1p1, h1p2, lvsum, ncout);
            __syncwarp(0x3u);
            if (ln == 0) { MBAR_ARRIVE(mPUB0); outb[i] = ncout; }
            MBAR_WAIT(mPAR1, ph);
            comb_lane(i + 1, par1, pub1, SM, n, nc, h0p0, h0p1, h0p2,
                      h1p0, h1p1, h1p2, lvsum, ncout);
            __syncwarp(0x3u);
            if (ln == 0) { MBAR_ARRIVE(mPUB1); outb[i + 1] = ncout; }
        }
        if (ln == 1) out[BB * DD + b] = lvsum;
    }
}

extern "C" void kernel_launch(void* const* d_in, const int* in_sizes, int n_in,
                              void* d_out, int out_size) {
    const float* xx   = (const float*)d_in[0];
    const float* muW0 = (const float*)d_in[1];
    const float* mub0 = (const float*)d_in[2];
    const float* muW1 = (const float*)d_in[3];
    const float* mub1 = (const float*)d_in[4];
    const float* muWo = (const float*)d_in[5];
    const float* mubo = (const float*)d_in[6];
    const float* lvW0 = (const float*)d_in[7];
    const float* lvb0 = (const float*)d_in[8];
    const float* lvW1 = (const float*)d_in[9];
    const float* lvb1 = (const float*)d_in[10];
    const float* lvWo = (const float*)d_in[11];
    const float* lvbo = (const float*)d_in[12];
    float* out = (float*)d_out;

    setup_kernel<<<512, 256>>>(muW0, muW1, muWo, mub0, mub1,
                               lvW0, lvW1, lvWo, lvb0, lvb1, mubo, lvbo);
    made_kernel<<<BB, 544>>>(xx, out);
}

// round 16
// speedup vs baseline: 1.8892x; 1.0022x over previous
#include <cuda_runtime.h>
#include <math.h>

#define DD 256
#define HH 512
#define BB 128
typedef unsigned long long ull;

__device__ __forceinline__ ull packf2(float lo, float hi) {
    return ((ull)__float_as_uint(hi) << 32) | (ull)__float_as_uint(lo);
}
__device__ __forceinline__ float lof(ull v) { return __uint_as_float((unsigned)v); }
__device__ __forceinline__ float hif(ull v) { return __uint_as_float((unsigned)(v >> 32)); }
__device__ __forceinline__ void ffma2(ull& d, ull a, ull b) {
    asm("fma.rn.f32x2 %0, %1, %2, %0;" : "+l"(d) : "l"(a), "l"(b));
}
__device__ __forceinline__ unsigned smem_u32(const void* p) {
    return (unsigned)__cvta_generic_to_shared(p);
}
#define MBAR_INIT(addr, cnt) \
    asm volatile("mbarrier.init.shared.b64 [%0], %1;" :: "r"(addr), "r"(cnt) : "memory")
#define MBAR_ARRIVE(addr) \
    asm volatile("mbarrier.arrive.shared.b64 _, [%0];" :: "r"(addr) : "memory")
#define MBAR_WAIT(addr, parity) do {                                          \
    unsigned _m = (addr), _p = (parity), _done;                               \
    asm volatile("{\n\t.reg .pred p;\n\t"                                     \
        "mbarrier.try_wait.parity.acquire.cta.shared::cta.b64 p, [%1], %2;\n\t" \
        "selp.b32 %0, 1, 0, p;\n\t}"                                          \
        : "=r"(_done) : "r"(_m), "r"(_p) : "memory");                         \
    if (!_done) {                                                             \
        asm volatile("{\n\t.reg .pred P1;\n\t"                                \
            "WL_%=:\n\t"                                                      \
            "mbarrier.try_wait.parity.acquire.cta.shared::cta.b64 P1, [%0], %1, 0x989680;\n\t" \
            "@P1 bra.uni WD_%=;\n\t"                                          \
            "bra.uni WL_%=;\n\t"                                              \
            "WD_%=:\n\t}"                                                     \
            :: "r"(_m), "r"(_p) : "memory");                                  \
    }                                                                         \
} while (0)

__device__ ulonglong2 g_wA[260 * 512];
__device__ ull g_wA2[260 * 512];
__device__ ull g_wO[260 * 512];
__device__ ull g_w3p[2 * 512];
__device__ float g_w3o[2 * 512];
__device__ float g_recS[256 * 40];
__device__ float g_recW[4 * 68];

__device__ __forceinline__ int permf(int p) {
    if (p < 3) return (p == 0) ? 0 : ((p == 1) ? 255 : 510);
    if (p < 6) { int q = p - 3; return (q == 0) ? 1 : ((q == 1) ? 256 : 511); }
    int d = 3 + ((p - 6) >> 1);
    return (((p - 6) & 1) == 0) ? (d - 1) : (d + 254);
}
__device__ __forceinline__ int degf(int p) {
    if (p < 3) return 1;
    if (p < 6) return 2;
    return 3 + ((p - 6) >> 1);
}
__device__ __forceinline__ int Pof(int k) {
    if (k <= 0) return 0;
    if (k == 1) return 3;
    int v = 2 * k + 2;
    return v > HH ? HH : v;
}
__device__ __forceinline__ float elu1(float a) {
    float e = __expf(a) - 1.f;
    return a > 0.f ? a : e;
}

__global__ void setup_kernel(
    const float* __restrict__ W0m, const float* __restrict__ W1m, const float* __restrict__ Wom,
    const float* __restrict__ b0m, const float* __restrict__ b1m,
    const float* __restrict__ W0l, const float* __restrict__ W1l, const float* __restrict__ Wol,
    const float* __restrict__ b0l, const float* __restrict__ b1l,
    const float* __restrict__ bom, const float* __restrict__ bol)
{
    int tid = blockIdx.x * blockDim.x + threadIdx.x;
    int stride = gridDim.x * blockDim.x;

    for (int idx = tid; idx < 256 * 512; idx += stride) {
        int i = idx >> 9, u = idx & 511;
        int du = degf(u), ou = permf(u);
        int onet = u >> 8, ocol = u & 255;
        const float* Wo = onet ? Wol : Wom;

        int w0row = i - 1 < 0 ? 0 : i - 1;
        float m0 = (du >= w0row + 1) ? 1.f : 0.f;
        float w0mu = m0 * W0m[ou * DD + w0row];
        float w0lv = m0 * W0l[ou * DD + w0row];

        int pB = Pof(i - 2);
        float w1s[2][2], wos[2];
#pragma unroll
        for (int s = 0; s < 2; s++) {
            int p = pB + s; if (p > HH - 1) p = HH - 1;
            int op = permf(p), dp = degf(p);
            float m1 = (du >= dp) ? 1.f : 0.f;
            w1s[s][0] = m1 * W1m[ou * HH + op];
            w1s[s][1] = m1 * W1l[ou * HH + op];
            float mo = (ocol >= dp) ? 1.f : 0.f;
            wos[s] = mo * Wo[ocol * HH + op];
        }
        g_wA[i * 512 + u] = make_ulonglong2(packf2(w0mu, w0lv), packf2(w1s[0][0], w1s[0][1]));
        g_wA2[i * 512 + u] = packf2(w1s[1][0], w1s[1][1]);
        g_wO[i * 512 + u] = packf2(wos[0], wos[1]);
    }
    for (int idx = tid; idx < 1024; idx += stride) {
        int j = idx >> 9, u = idx & 511;
        int du = degf(u), ou = permf(u);
        int onet = u >> 8, ocol = u & 255;
        const float* Wo = onet ? Wol : Wom;
        int p = (j == 0) ? 2 : 5;
        int op = permf(p), dp = degf(p);
        float m1 = (du >= dp) ? 1.f : 0.f;
        float mo = (ocol >= dp) ? 1.f : 0.f;
        g_w3p[idx] = packf2(m1 * W1m[ou * HH + op], m1 * W1l[ou * HH + op]);
        g_w3o[idx] = mo * Wo[ocol * HH + op];
    }
    for (int i = tid; i < 256; i += stride) {
        int cB = Pof(i - 1), cc = Pof(i) - cB;
        int pB = Pof(i - 2), cp = Pof(i - 1) - pB;
        {
            float* r = g_recS + i * 40;
            for (int k = 0; k < 40; k++) r[k] = 0.f;
            int c2 = cc < 2 ? cc : 2, p2 = cp < 2 ? cp : 2;
            for (int s = 0; s < c2; s++) {
                int p = permf(cB + s);
                if (i >= 1) { r[0 + 2 * s] = W0m[p * DD + (i - 1)]; r[1 + 2 * s] = W0l[p * DD + (i - 1)]; }
                r[4 + 2 * s] = b0m[p];  r[5 + 2 * s] = b0l[p];
                r[8 + 2 * s] = b1m[p];  r[9 + 2 * s] = b1l[p];
                r[32 + 2 * s] = Wom[i * HH + p]; r[33 + 2 * s] = Wol[i * HH + p];
            }
            for (int sp = 0; sp < p2; sp++) {
                int pp = permf(pB + sp);
                r[28 + 2 * sp] = Wom[i * HH + pp]; r[29 + 2 * sp] = Wol[i * HH + pp];
                for (int sc = 0; sc < c2; sc++) {
                    int g = permf(cB + sc);
                    r[12 + sp * 4 + 2 * sc] = W1m[g * HH + pp];
                    r[13 + sp * 4 + 2 * sc] = W1l[g * HH + pp];
                }
            }
            for (int sp = 0; sp < c2; sp++)
                for (int sc = 0; sc < c2; sc++) {
                    int pp = permf(cB + sp), g = permf(cB + sc);
                    r[20 + sp * 4 + 2 * sc] = W1m[g * HH + pp];
                    r[21 + sp * 4 + 2 * sc] = W1l[g * HH + pp];
                }
            r[36] = bom[i]; r[37] = bol[i];
        }
        if (i < 4) {
            float* r = g_recW + i * 68;
            for (int k = 0; k < 68; k++) r[k] = 0.f;
            for (int s = 0; s < cc; s++) {
                int p = permf(cB + s);
                if (i >= 1) { r[0 + 2 * s] = W0m[p * DD + (i - 1)]; r[1 + 2 * s] = W0l[p * DD + (i - 1)]; }
                r[6 + 2 * s] = b0m[p];  r[7 + 2 * s] = b0l[p];
                r[12 + 2 * s] = b1m[p]; r[13 + 2 * s] = b1l[p];
                r[60 + 2 * s] = Wom[i * HH + p]; r[61 + 2 * s] = Wol[i * HH + p];
            }
            for (int sp = 0; sp < cp; sp++) {
                int pp = permf(pB + sp);
                r[54 + 2 * sp] = Wom[i * HH + pp]; r[55 + 2 * sp] = Wol[i * HH + pp];
                for (int sc = 0; sc < cc; sc++) {
                    int g = permf(cB + sc);
                    r[18 + sp * 6 + 2 * sc] = W1m[g * HH + pp];
                    r[19 + sp * 6 + 2 * sc] = W1l[g * HH + pp];
                }
            }
            for (int sp = 0; sp < cc; sp++)
                for (int sc = 0; sc < cc; sc++) {
                    int pp = permf(cB + sp), g = permf(cB + sc);
                    r[36 + sp * 6 + 2 * sc] = W1m[g * HH + pp];
                    r[37 + sp * 6 + 2 * sc] = W1l[g * HH + pp];
                }
            r[66] = bom[i]; r[67] = bol[i];
        }
    }
}

#define OFF_RECS 0
#define OFF_RECW 10240
#define OFF_XS   10512
#define OFF_PUB  10768
#define OFF_PAR  10800
#define OFF_MBAR 10832   // 4 mbarriers (u64) => 8 floats
#define SM_FLOATS 10840

// 2-lane net-split combiner step (identical math to R14)
__device__ __forceinline__ void comb_lane(
    int i, const float* __restrict__ pr, float* __restrict__ pu,
    const float* __restrict__ SMbase, int n,
    float& nc, float& h0p0, float& h0p1, float& h0p2,
    float& h1p0, float& h1p1, float& h1p2,
    float& lvsum, float& ncout)
{
    const float xi = SMbase[OFF_XS + i];
    float h0c0, h0c1, h0c2 = 0.f, h1c0, h1c1, h1c2 = 0.f;
    float m;
    if (i >= 4) {
        const float* r = SMbase + OFF_RECS + i * 40 + n;
        h0c0 = elu1(pr[0 + n] + nc * r[0] + r[4]);
        h0c1 = elu1(pr[4 + n] + nc * r[2] + r[6]);
        float a0 = pr[2 + n] + r[8];
        a0 = fmaf(h0p0, r[12], a0); a0 = fmaf(h0p1, r[16], a0);
        a0 = fmaf(h0c0, r[20], a0); a0 = fmaf(h0c1, r[24], a0);
        h1c0 = elu1(a0);
        float a1 = pr[6 + n] + r[10];
        a1 = fmaf(h0p0, r[14], a1); a1 = fmaf(h0p1, r[18], a1);
        a1 = fmaf(h0c0, r[22], a1); a1 = fmaf(h0c1, r[26], a1);
        h1c1 = elu1(a1);
        m = pr[12 + n] + r[36];
        m = fmaf(h1p0, r[28], m); m = fmaf(h1p1, r[30], m);
        m = fmaf(h1c0, r[32], m); m = fmaf(h1c1, r[34], m);
    } else {
        const float* r = SMbase + OFF_RECW + i * 68 + n;
        h0c0 = elu1(pr[0 + n] + nc * r[0] + r[6]);
        h0c1 = elu1(pr[4 + n] + nc * r[2] + r[8]);
        h0c2 = elu1(pr[8 + n] + nc * r[4] + r[10]);
        float a0 = pr[2 + n] + r[12];
        a0 = fmaf(h0p0, r[18], a0); a0 = fmaf(h0p1, r[24], a0); a0 = fmaf(h0p2, r[30], a0);
        a0 = fmaf(h0c0, r[36], a0); a0 = fmaf(h0c1, r[42], a0); a0 = fmaf(h0c2, r[48], a0);
        h1c0 = elu1(a0);
        float a1 = pr[6 + n] + r[14];
        a1 = fmaf(h0p0, r[20], a1); a1 = fmaf(h0p1, r[26], a1); a1 = fmaf(h0p2, r[32], a1);
        a1 = fmaf(h0c0, r[38], a1); a1 = fmaf(h0c1, r[44], a1); a1 = fmaf(h0c2, r[50], a1);
        h1c1 = elu1(a1);
        float a2 = pr[10 + n] + r[16];
        a2 = fmaf(h0p0, r[22], a2); a2 = fmaf(h0p1, r[28], a2); a2 = fmaf(h0p2, r[34], a2);
        a2 = fmaf(h0c0, r[40], a2); a2 = fmaf(h0c1, r[46], a2); a2 = fmaf(h0c2, r[52], a2);
        h1c2 = elu1(a2);
        m = pr[12 + n] + r[66];
        m = fmaf(h1p0, r[54], m); m = fmaf(h1p1, r[56], m); m = fmaf(h1p2, r[58], m);
        m = fmaf(h1c0, r[60], m); m = fmaf(h1c1, r[62], m); m = fmaf(h1c2, r[64], m);
    }
    const float other = __shfl_xor_sync(0x3u, m, 1);
    const float mu = (n == 0) ? m : other;
    const float lv = (n == 0) ? other : m;
    const float ls = 0.5f * lv;
    const float ncn = (xi - mu) * __expf(-ls);
    nc = ncn;
    if (n) lvsum += ls;
    ncout = ncn;
    pu[n] = ncn;
    pu[2 + n] = h0c0; pu[4 + n] = h0c1;
    pu[6 + 2 * n] = h1c0; pu[7 + 2 * n] = h1c1;
    if (i < 4) { pu[10 + n] = h0c2; pu[12 + n] = h1c2; }
    h0p0 = h0c0; h0p1 = h0c1; h0p2 = h0c2;
    h1p0 = h1c0; h1p1 = h1c1; h1p2 = h1c2;
}

__device__ __forceinline__ void wide_step(
    int i, const float* __restrict__ pb, const float* __restrict__ pbh,
    const float* __restrict__ pb12,
    ulonglong2 Wa, ull Wa2, ull Wo,
    ull& A0, ull& A1, ull& AO, float& aoutC,
    int pubA, int pubO, float* __restrict__ pwA, float* __restrict__ pwO,
    ull w3p2, ull w3p3, float w3o2, float w3o3)
{
    if (i <= pubA) {
        const ull nc2  = *(const ull*)(pb + 0);
        const ull h0s0 = *(const ull*)(pb + 2);
        const ull h0s1 = *(const ull*)(pb + 4);
        ffma2(A0, nc2, Wa.x);
        ffma2(A1, h0s0, Wa.y);
        ffma2(A1, h0s1, Wa2);
        if ((unsigned)(i - 2) < 2u) {
            const ull h0s2 = *(const ull*)(pb + 10);
            ffma2(A1, h0s2, (i == 2) ? w3p2 : w3p3);
        }
        if (i == pubA) { *(ull*)(pwA + 0) = A0; *(ull*)(pwA + 2) = A1; }
    }
    if (i <= pubO) {
        const ull h1p = *(const ull*)pbh;
        ffma2(AO, h1p, Wo);
        if ((unsigned)(i - 2) < 2u)
            aoutC = fmaf(*pb12, (i == 2) ? w3o2 : w3o3, aoutC);
        if (i == pubO) *pwO = lof(AO) + hif(AO) + aoutC;
    }
}

__global__ __launch_bounds__(544, 1) void made_kernel(
    const float* __restrict__ x, float* __restrict__ out)
{
    __shared__ __align__(16) float SM[SM_FLOATS];

    const int tid = threadIdx.x;
    const int b = blockIdx.x;

    {
        const float4* src = (const float4*)g_recS;
        float4* dst = (float4*)(SM + OFF_RECS);
        for (int k = tid; k < (256 * 40) / 4; k += 544) dst[k] = src[k];
        for (int k = tid; k < 4 * 68; k += 544) SM[OFF_RECW + k] = g_recW[k];
        if (tid < 256) SM[OFF_XS + tid] = x[b * DD + tid];
        for (int k = tid; k < 64; k += 544) SM[OFF_PUB + k] = 0.f;
    }
    // mbarriers: [0]=PAR0 [1]=PAR1 [2]=PUB0 [3]=PUB1
    const unsigned mb = smem_u32(SM + OFF_MBAR);
    const unsigned mPAR0 = mb, mPAR1 = mb + 8, mPUB0 = mb + 16, mPUB1 = mb + 24;
    if (tid == 0) {
        MBAR_INIT(mPAR0, 16);
        MBAR_INIT(mPAR1, 16);
        MBAR_INIT(mPUB0, 1);
        MBAR_INIT(mPUB1, 1);
    }
    __syncthreads();

    float* const pub0 = SM + OFF_PUB;
    float* const pub1 = SM + OFF_PUB + 16;
    float* const par0 = SM + OFF_PAR;
    float* const par1 = SM + OFF_PAR + 16;
    float* const outb = out + b * DD;

    if (tid < 512) {
        // ---- wide warps ----
        const int u = tid;
        const int du = degf(u);
        const int su = u - Pof(du - 1);
        const int onet = (tid >> 8) & 1;
        const int ocol = tid & 255;
        const int pubA = du - 1;
        const int pubO = ocol - 1;
        const int off = (su < 2) ? (su << 2) : 8;
        const bool elect = ((tid & 31) == 0);

        float* const pwA0 = par0 + off;
        float* const pwA1 = par1 + off;
        float* const pwO0 = par0 + 12 + onet;
        float* const pwO1 = par1 + 12 + onet;
        const float* const pbh0 = pub0 + 6 + 2 * onet;
        const float* const pbh1 = pub1 + 6 + 2 * onet;
        const float* const pb120 = pub0 + 12 + onet;
        const float* const pb121 = pub1 + 12 + onet;

        ull A0 = 0, A1 = 0, AO = 0;
        float aoutC = 0.f;

        const ulonglong2* wA = g_wA + u;
        const ull* wA2 = g_wA2 + u;
        const ull* wO = g_wO + u;
        ulonglong2 Wa0 = wA[0],   Wa1 = wA[512];
        ull Wa20 = wA2[0], Wa21 = wA2[512];
        ull Wo0 = wO[0],   Wo1 = wO[512];
        const ull w3p2 = g_w3p[u], w3p3 = g_w3p[512 + u];
        const float w3o2 = g_w3o[u], w3o3 = g_w3o[512 + u];

        if (elect) MBAR_ARRIVE(mPAR0);   // prime par(0) = zeros

#pragma unroll 1
        for (int t = 0; t < 128; t++) {
            const unsigned ph = (unsigned)(t & 1);
            const int i = 2 * t;
            // even step i: consume pub(i-1) in pub1 buffer, publish par(i+1) in par1
            MBAR_WAIT(mPUB1, ph);
            wide_step(i, pub1, pbh1, pb121, Wa0, Wa20, Wo0, A0, A1, AO, aoutC,
                      pubA, pubO, pwA1, pwO1, w3p2, w3p3, w3o2, w3o3);
            __syncwarp();
            if (elect) MBAR_ARRIVE(mPAR1);
            if (i + 2 <= pubA) { Wa0 = wA[(i + 2) << 9]; Wa20 = wA2[(i + 2) << 9]; }
            if (i + 2 <= pubO) { Wo0 = wO[(i + 2) << 9]; }
            // odd step i+1: consume pub(i) in pub0, publish par(i+2) in par0
            MBAR_WAIT(mPUB0, ph);
            wide_step(i + 1, pub0, pbh0, pb120, Wa1, Wa21, Wo1, A0, A1, AO, aoutC,
                      pubA, pubO, pwA0, pwO0, w3p2, w3p3, w3o2, w3o3);
            __syncwarp();
            if (elect) MBAR_ARRIVE(mPAR0);
            if (i + 3 <= pubA) { Wa1 = wA[(i + 3) << 9]; Wa21 = wA2[(i + 3) << 9]; }
            if (i + 3 <= pubO) { Wo1 = wO[(i + 3) << 9]; }
        }
    } else {
        // ---- combiner warp (warp 16): lanes 0,1 compute (net-split) ----
        const int ln = tid - 512;
        if (ln >= 2) return;
        const int n = ln;
        float h0p0 = 0.f, h0p1 = 0.f, h0p2 = 0.f;
        float h1p0 = 0.f, h1p1 = 0.f, h1p2 = 0.f;
        float nc = 0.f, lvsum = 0.f, ncout;

        if (ln == 0) MBAR_ARRIVE(mPUB1);   // prime pub(-1) = zeros

#pragma unroll 1
        for (int t = 0; t < 128; t++) {
            const unsigned ph = (unsigned)(t & 1);
            const int i = 2 * t;
            MBAR_WAIT(mPAR0, ph);
            comb_lane(i, par0, pub0, SM, n, nc, h0p0, h0p1, h0p2,
                      h1p0, h1p1, h1p2, lvsum, ncout);
            __syncwarp(0x3u);
            if (ln == 0) { MBAR_ARRIVE(mPUB0); outb[i] = ncout; }
            MBAR_WAIT(mPAR1, ph);
            comb_lane(i + 1, par1, pub1, SM, n, nc, h0p0, h0p1, h0p2,
                      h1p0, h1p1, h1p2, lvsum, ncout);
            __syncwarp(0x3u);
            if (ln == 0) { MBAR_ARRIVE(mPUB1); outb[i + 1] = ncout; }
        }
        if (ln == 1) out[BB * DD + b] = lvsum;
    }
}

extern "C" void kernel_launch(void* const* d_in, const int* in_sizes, int n_in,
                              void* d_out, int out_size) {
    const float* xx   = (const float*)d_in[0];
    const float* muW0 = (const float*)d_in[1];
    const float* mub0 = (const float*)d_in[2];
    const float* muW1 = (const float*)d_in[3];
    const float* mub1 = (const float*)d_in[4];
    const float* muWo = (const float*)d_in[5];
    const float* mubo = (const float*)d_in[6];
    const float* lvW0 = (const float*)d_in[7];
    const float* lvb0 = (const float*)d_in[8];
    const float* lvW1 = (const float*)d_in[9];
    const float* lvb1 = (const float*)d_in[10];
    const float* lvWo = (const float*)d_in[11];
    const float* lvbo = (const float*)d_in[12];
    float* out = (float*)d_out;

    setup_kernel<<<512, 256>>>(muW0, muW1, muWo, mub0, mub1,
                               lvW0, lvW1, lvWo, lvb0, lvb1, mubo, lvbo);
    made_kernel<<<BB, 544>>>(xx, out);
}